// round 2
// baseline (speedup 1.0000x reference)
#include <cuda_runtime.h>

#define NN 100000
#define NE 1600000
#define BN_EPS 1e-5f

// ---------------- scratch (static __device__, no allocs) ----------------
__device__ __align__(16) float g_hs [(size_t)NN * 128];   // pre-scaled h (dinv[row]*h)
__device__ __align__(16) float g_agg[(size_t)NN * 128];   // aggregation accumulator
__device__ __align__(16) float g_x2 [(size_t)NN * 128];   // normalized activations
__device__ float g_dinv[NN];
__device__ int   g_deg [NN];
__device__ int   g_src [NE];
__device__ int   g_dst [NE];
__device__ int   g_is64;
__device__ float g_stats[512];              // sum/sumsq: layer1 [0:256), layer2 [256:512)
__device__ float g_sc[512];                 // scale/shift: layer1 [0:256), layer2 [256:512)

// ---------------- detect edge_index dtype (int64 vs int32) ----------------
// int64 little-endian with values < 2^31 => every odd 32-bit word is 0.
__global__ void k_detect(const int* __restrict__ ei32) {
    int is64 = 1;
    for (int j = 0; j < 64; j++)
        if (ei32[2 * j + 1] != 0) { is64 = 0; break; }
    g_is64 = is64;
}

// ---------------- convert to int32 src/dst (clamped) ----------------
__global__ void k_convert(const int* __restrict__ ei32) {
    int e = blockIdx.x * blockDim.x + threadIdx.x;
    if (e >= NE) return;
    int s, d;
    if (g_is64) {
        s = ei32[2 * (size_t)e];
        d = ei32[2 * ((size_t)NE + e)];
    } else {
        s = ei32[e];
        d = ei32[NE + e];
    }
    s = min(max(s, 0), NN - 1);
    d = min(max(d, 0), NN - 1);
    g_src[e] = s;
    g_dst[e] = d;
}

// ---------------- init: zero deg + stats ----------------
__global__ void k_init() {
    int i = blockIdx.x * blockDim.x + threadIdx.x;
    if (i < NN)  g_deg[i] = 0;
    if (i < 512) g_stats[i] = 0.f;
}

// ---------------- degree count (dst occurrences) ----------------
__global__ void k_deg() {
    int e = blockIdx.x * blockDim.x + threadIdx.x;
    if (e < NE) atomicAdd(&g_deg[g_dst[e]], 1);
}

// ---------------- dinv = rsqrt(deg + 1 self loop) ----------------
__global__ void k_dinv() {
    int i = blockIdx.x * blockDim.x + threadIdx.x;
    if (i < NN) g_dinv[i] = rsqrtf((float)(g_deg[i] + 1));
}

// ---------------- SGEMM: h = A @ W, epilogue hs = h*dinv[row]; agg = hs ----------
// A: [NN,128] row-major (external x or g_x2), W: [128,NC] row-major.
// 128x128 tile / block, 256 threads, 8x8 per thread, BK=16.
template <int NC, bool USE_X2>
__global__ void __launch_bounds__(256) k_gemm(const float* __restrict__ Ain,
                                              const float* __restrict__ W) {
    const float* __restrict__ A = USE_X2 ? g_x2 : Ain;
    __shared__ float As[16][128];
    __shared__ float Bs[16][128];

    const int tid  = threadIdx.x;
    const int row0 = blockIdx.x * 128;
    const int tx = tid & 15;
    const int ty = tid >> 4;

    float acc[8][8];
#pragma unroll
    for (int i = 0; i < 8; i++)
#pragma unroll
        for (int j = 0; j < 8; j++) acc[i][j] = 0.f;

    for (int kb = 0; kb < 128; kb += 16) {
        // load A tile (128 rows x 16 k), transposed into As[k][m]
#pragma unroll
        for (int i = 0; i < 2; i++) {
            int f  = tid * 2 + i;      // 0..511
            int m  = f >> 2;
            int k4 = f & 3;
            int r  = row0 + m;
            float4 v = make_float4(0.f, 0.f, 0.f, 0.f);
            if (r < NN) v = *(const float4*)&A[(size_t)r * 128 + kb + k4 * 4];
            As[k4 * 4 + 0][m] = v.x;
            As[k4 * 4 + 1][m] = v.y;
            As[k4 * 4 + 2][m] = v.z;
            As[k4 * 4 + 3][m] = v.w;
        }
        // load W tile (16 k x NC cols, zero-padded to 128)
#pragma unroll
        for (int i = 0; i < 2; i++) {
            int f  = tid * 2 + i;
            int k  = f >> 5;
            int c4 = f & 31;
            float4 v = make_float4(0.f, 0.f, 0.f, 0.f);
            if (c4 * 4 < NC) v = *(const float4*)&W[(size_t)(kb + k) * NC + c4 * 4];
            *(float4*)&Bs[k][c4 * 4] = v;
        }
        __syncthreads();

#pragma unroll
        for (int k = 0; k < 16; k++) {
            float a[8], b[8];
#pragma unroll
            for (int i = 0; i < 8; i++) a[i] = As[k][ty * 8 + i];
#pragma unroll
            for (int j = 0; j < 8; j++) b[j] = Bs[k][tx * 8 + j];
#pragma unroll
            for (int i = 0; i < 8; i++)
#pragma unroll
                for (int j = 0; j < 8; j++) acc[i][j] = fmaf(a[i], b[j], acc[i][j]);
        }
        __syncthreads();
    }

    // epilogue: hs = acc*dinv[r]; agg = hs (self-loop init)
#pragma unroll
    for (int i = 0; i < 8; i++) {
        int r = row0 + ty * 8 + i;
        if (r >= NN) break;
        float d = g_dinv[r];
#pragma unroll
        for (int j = 0; j < 8; j += 4) {
            int c = tx * 8 + j;
            if (c < NC) {
                float4 v;
                v.x = acc[i][j + 0] * d;
                v.y = acc[i][j + 1] * d;
                v.z = acc[i][j + 2] * d;
                v.w = acc[i][j + 3] * d;
                *(float4*)&g_hs [(size_t)r * NC + c] = v;
                *(float4*)&g_agg[(size_t)r * NC + c] = v;
            }
        }
    }
}

// ---------------- edge scatter: agg[dst] += hs[src], C=128 (warp per edge) --------
__global__ void k_scatter128() {
    int gid  = blockIdx.x * blockDim.x + threadIdx.x;
    int e    = gid >> 5;
    if (e >= NE) return;
    int lane = gid & 31;
    int s = g_src[e];
    int d = g_dst[e];
    float4 v = *(const float4*)&g_hs[(size_t)s * 128 + lane * 4];
    atomicAdd((float4*)&g_agg[(size_t)d * 128 + lane * 4], v);
}

// ---------------- edge scatter: C=40 (16 threads per edge, 10 active) -------------
__global__ void k_scatter40() {
    int gid  = blockIdx.x * blockDim.x + threadIdx.x;
    int e    = gid >> 4;
    if (e >= NE) return;
    int lane = gid & 15;
    if (lane >= 10) return;
    int s = g_src[e];
    int d = g_dst[e];
    float4 v = *(const float4*)&g_hs[(size_t)s * 40 + lane * 4];
    atomicAdd((float4*)&g_agg[(size_t)d * 40 + lane * 4], v);
}

// ---------------- post-scale + bias (in place) + BN partial stats ------------------
__global__ void k_stats(const float* __restrict__ bias, int statsOff) {
    int c    = threadIdx.x;         // 128 threads
    int row0 = blockIdx.x * 64;
    float b  = bias[c];
    float s = 0.f, s2 = 0.f;
    int rend = row0 + 64;
    if (rend > NN) rend = NN;
#pragma unroll 4
    for (int r = row0; r < rend; r++) {
        float v = g_agg[(size_t)r * 128 + c] * g_dinv[r] + b;
        g_agg[(size_t)r * 128 + c] = v;
        s  += v;
        s2 += v * v;
    }
    atomicAdd(&g_stats[statsOff + c], s);
    atomicAdd(&g_stats[statsOff + 128 + c], s2);
}

// ---------------- finalize BN: scale/shift per channel -----------------------------
__global__ void k_finalize(const float* __restrict__ gamma, const float* __restrict__ beta,
                           int statsOff, int scOff) {
    int c = threadIdx.x;            // 128 threads, 1 block
    float inv_n = 1.f / (float)NN;
    float mean = g_stats[statsOff + c] * inv_n;
    float var  = g_stats[statsOff + 128 + c] * inv_n - mean * mean;
    float inv  = rsqrtf(var + BN_EPS);
    float sc   = gamma[c] * inv;
    g_sc[scOff + c]       = sc;
    g_sc[scOff + 128 + c] = beta[c] - mean * sc;
}

// ---------------- normalize + ReLU -> g_x2 ----------------------------------------
__global__ void k_norm(int scOff) {
    int i4 = blockIdx.x * blockDim.x + threadIdx.x;   // float4 index
    const int total4 = NN * 128 / 4;
    if (i4 >= total4) return;
    int c = (i4 * 4) & 127;
    float4 v = ((const float4*)g_agg)[i4];
    v.x = fmaxf(fmaf(v.x, g_sc[scOff + c + 0], g_sc[scOff + 128 + c + 0]), 0.f);
    v.y = fmaxf(fmaf(v.y, g_sc[scOff + c + 1], g_sc[scOff + 128 + c + 1]), 0.f);
    v.z = fmaxf(fmaf(v.z, g_sc[scOff + c + 2], g_sc[scOff + 128 + c + 2]), 0.f);
    v.w = fmaxf(fmaf(v.w, g_sc[scOff + c + 3], g_sc[scOff + 128 + c + 3]), 0.f);
    ((float4*)g_x2)[i4] = v;
}

// ---------------- final: out = agg3*dinv + b3 (C=40) -------------------------------
__global__ void k_out(const float* __restrict__ b3, float* __restrict__ out) {
    int i4 = blockIdx.x * blockDim.x + threadIdx.x;   // float4 index
    const int total4 = NN * 40 / 4;
    if (i4 >= total4) return;
    int flat = i4 * 4;
    int r = flat / 40;
    int c = flat % 40;
    float d = g_dinv[r];
    float4 v = ((const float4*)g_agg)[i4];
    v.x = fmaf(v.x, d, b3[c + 0]);
    v.y = fmaf(v.y, d, b3[c + 1]);
    v.z = fmaf(v.z, d, b3[c + 2]);
    v.w = fmaf(v.w, d, b3[c + 3]);
    ((float4*)out)[i4] = v;
}

// ---------------- launch ----------------
extern "C" void kernel_launch(void* const* d_in, const int* in_sizes, int n_in,
                              void* d_out, int out_size) {
    const float* x    = (const float*)d_in[0];
    const int*   ei32 = (const int*)d_in[1];
    const float* W1 = (const float*)d_in[2];
    const float* b1 = (const float*)d_in[3];
    const float* g1 = (const float*)d_in[4];
    const float* t1 = (const float*)d_in[5];
    const float* W2 = (const float*)d_in[6];
    const float* b2 = (const float*)d_in[7];
    const float* g2 = (const float*)d_in[8];
    const float* t2 = (const float*)d_in[9];
    const float* W3 = (const float*)d_in[10];
    const float* b3 = (const float*)d_in[11];
    float* out = (float*)d_out;

    const int gemmBlocks  = (NN + 127) / 128;            // 782
    const int sc128Blocks = (NE * 32 + 255) / 256;       // 200000
    const int sc40Blocks  = (NE * 16 + 255) / 256;       // 100000
    const int statBlocks  = (NN + 63) / 64;              // 1563

    k_detect<<<1, 1>>>(ei32);
    k_convert<<<(NE + 255) / 256, 256>>>(ei32);
    k_init<<<(NN + 255) / 256, 256>>>();
    k_deg <<<(NE + 255) / 256, 256>>>();
    k_dinv<<<(NN + 255) / 256, 256>>>();

    // layer 1
    k_gemm<128, false><<<gemmBlocks, 256>>>(x, W1);
    k_scatter128<<<sc128Blocks, 256>>>();
    k_stats<<<statBlocks, 128>>>(b1, 0);
    k_finalize<<<1, 128>>>(g1, t1, 0, 0);
    k_norm<<<(NN * 128 / 4 + 255) / 256, 256>>>(0);

    // layer 2
    k_gemm<128, true><<<gemmBlocks, 256>>>(nullptr, W2);
    k_scatter128<<<sc128Blocks, 256>>>();
    k_stats<<<statBlocks, 128>>>(b2, 256);
    k_finalize<<<1, 128>>>(g2, t2, 256, 256);
    k_norm<<<(NN * 128 / 4 + 255) / 256, 256>>>(256);

    // layer 3 (output, C=40)
    k_gemm<40, true><<<gemmBlocks, 256>>>(nullptr, W3);
    k_scatter40<<<sc40Blocks, 256>>>();
    k_out<<<(NN * 40 / 4 + 255) / 256, 256>>>(b3, out);
}

// round 3
// speedup vs baseline: 1.8742x; 1.8742x over previous
#include <cuda_runtime.h>

#define NN 100000
#define NE 1600000
#define BN_EPS 1e-5f
#define SCAN_BLK 1024
#define NSB ((NN + SCAN_BLK - 1) / SCAN_BLK)   // 98

// ---------------- scratch ----------------
__device__ __align__(16) float g_hs [(size_t)NN * 128];   // h * dinv[row]
__device__ __align__(16) float g_agg[(size_t)NN * 128];   // aggregated + bias (pre-BN)
__device__ float g_dinv[NN];
__device__ int   g_deg [NN];
__device__ int   g_off [NN + 1];
__device__ int   g_cur [NN];
__device__ int   g_src [NE];
__device__ int   g_dst [NE];
__device__ int   g_esrc[NE];       // CSR: sources grouped by dst
__device__ int   g_bsum[NSB];
__device__ int   g_is64;
__device__ float g_stats[512];     // sum/sumsq: L1 [0:256), L2 [256:512)
__device__ float g_sc[512];        // scale/shift: L1 [0:256), L2 [256:512)

// ---------------- detect edge_index dtype (int64 vs int32) ----------------
__global__ void k_detect(const int* __restrict__ ei32) {
    int is64 = 1;
    for (int j = 0; j < 64; j++)
        if (ei32[2 * j + 1] != 0) { is64 = 0; break; }
    g_is64 = is64;
}

// ---------------- init: zero deg + stats ----------------
__global__ void k_init() {
    int i = blockIdx.x * blockDim.x + threadIdx.x;
    if (i < NN)  g_deg[i] = 0;
    if (i < 512) g_stats[i] = 0.f;
}

// ---------------- convert to int32 src/dst (clamped) + dst histogram ----------
__global__ void k_convert(const int* __restrict__ ei32) {
    int e = blockIdx.x * blockDim.x + threadIdx.x;
    if (e >= NE) return;
    int s, d;
    if (g_is64) {
        s = ei32[2 * (size_t)e];
        d = ei32[2 * ((size_t)NE + e)];
    } else {
        s = ei32[e];
        d = ei32[NE + e];
    }
    s = min(max(s, 0), NN - 1);
    d = min(max(d, 0), NN - 1);
    g_src[e] = s;
    g_dst[e] = d;
    atomicAdd(&g_deg[d], 1);
}

// ---------------- dinv = rsqrt(deg + 1) ----------------
__global__ void k_dinv() {
    int i = blockIdx.x * blockDim.x + threadIdx.x;
    if (i < NN) g_dinv[i] = rsqrtf((float)(g_deg[i] + 1));
}

// ---------------- scan stage 1: per-block sums ----------------
__global__ void k_bsum() {
    __shared__ int ws[8];
    int b = blockIdx.x, tid = threadIdx.x;
    int i = b * SCAN_BLK + tid * 4;
    int s = 0;
#pragma unroll
    for (int j = 0; j < 4; j++) { int idx = i + j; if (idx < NN) s += g_deg[idx]; }
#pragma unroll
    for (int o = 16; o; o >>= 1) s += __shfl_down_sync(~0u, s, o);
    if ((tid & 31) == 0) ws[tid >> 5] = s;
    __syncthreads();
    if (tid == 0) { int t = 0; for (int j = 0; j < 8; j++) t += ws[j]; g_bsum[b] = t; }
}

// ---------------- scan stage 2: exclusive scan of block sums ----------------
__global__ void k_scanb() {
    int run = 0;
    for (int i = 0; i < NSB; i++) { int t = g_bsum[i]; g_bsum[i] = run; run += t; }
    g_off[NN] = run;
}

// ---------------- scan stage 3: per-block exclusive scan -> offsets + cursor ----
__global__ void k_off() {
    __shared__ int wsum[8];
    int b = blockIdx.x, tid = threadIdx.x;
    int i0 = b * SCAN_BLK + tid * 4;
    int d0 = (i0 + 0 < NN) ? g_deg[i0 + 0] : 0;
    int d1 = (i0 + 1 < NN) ? g_deg[i0 + 1] : 0;
    int d2 = (i0 + 2 < NN) ? g_deg[i0 + 2] : 0;
    int d3 = (i0 + 3 < NN) ? g_deg[i0 + 3] : 0;
    int t = d0 + d1 + d2 + d3;
    int lane = tid & 31, w = tid >> 5;
    int v = t;
#pragma unroll
    for (int o = 1; o < 32; o <<= 1) { int u = __shfl_up_sync(~0u, v, o); if (lane >= o) v += u; }
    if (lane == 31) wsum[w] = v;
    __syncthreads();
    if (tid == 0) { int run = 0; for (int j = 0; j < 8; j++) { int x = wsum[j]; wsum[j] = run; run += x; } }
    __syncthreads();
    int excl = wsum[w] + (v - t) + g_bsum[b];
    int e0 = excl, e1 = e0 + d0, e2 = e1 + d1, e3 = e2 + d2;
    if (i0 + 0 < NN) { g_off[i0 + 0] = e0; g_cur[i0 + 0] = e0; }
    if (i0 + 1 < NN) { g_off[i0 + 1] = e1; g_cur[i0 + 1] = e1; }
    if (i0 + 2 < NN) { g_off[i0 + 2] = e2; g_cur[i0 + 2] = e2; }
    if (i0 + 3 < NN) { g_off[i0 + 3] = e3; g_cur[i0 + 3] = e3; }
}

// ---------------- bucket placement (order within bucket arbitrary) --------------
__global__ void k_place() {
    int e = blockIdx.x * blockDim.x + threadIdx.x;
    if (e >= NE) return;
    int d = g_dst[e];
    int pos = atomicAdd(&g_cur[d], 1);
    g_esrc[pos] = g_src[e];
}

// ---------------- SGEMM 128x128 tile: hs = (norm?(relu(A*sc+sh)):A) @ W * dinv ----
template <bool NORM>
__global__ void __launch_bounds__(256) k_gemm128(const float* __restrict__ Ain,
                                                 const float* __restrict__ W, int scOff) {
    const float* __restrict__ A = NORM ? g_agg : Ain;
    __shared__ float As[16][128];
    __shared__ float Bs[16][128];
    __shared__ float sc_s[128], sh_s[128];

    const int tid = threadIdx.x;
    if (NORM && tid < 128) {
        sc_s[tid] = g_sc[scOff + tid];
        sh_s[tid] = g_sc[scOff + 128 + tid];
    }
    __syncthreads();

    const int row0 = blockIdx.x * 128;
    const int tx = tid & 15;
    const int ty = tid >> 4;

    float acc[8][8];
#pragma unroll
    for (int i = 0; i < 8; i++)
#pragma unroll
        for (int j = 0; j < 8; j++) acc[i][j] = 0.f;

    for (int kb = 0; kb < 128; kb += 16) {
#pragma unroll
        for (int i = 0; i < 2; i++) {
            int f = tid * 2 + i;         // 0..511
            int m = f >> 2;
            int k4 = f & 3;
            int r = row0 + m;
            float4 v = make_float4(0.f, 0.f, 0.f, 0.f);
            if (r < NN) v = *(const float4*)&A[(size_t)r * 128 + kb + k4 * 4];
            if (NORM) {
                int c = kb + k4 * 4;
                v.x = fmaxf(fmaf(v.x, sc_s[c + 0], sh_s[c + 0]), 0.f);
                v.y = fmaxf(fmaf(v.y, sc_s[c + 1], sh_s[c + 1]), 0.f);
                v.z = fmaxf(fmaf(v.z, sc_s[c + 2], sh_s[c + 2]), 0.f);
                v.w = fmaxf(fmaf(v.w, sc_s[c + 3], sh_s[c + 3]), 0.f);
            }
            As[k4 * 4 + 0][m] = v.x;
            As[k4 * 4 + 1][m] = v.y;
            As[k4 * 4 + 2][m] = v.z;
            As[k4 * 4 + 3][m] = v.w;
        }
#pragma unroll
        for (int i = 0; i < 2; i++) {
            int f = tid * 2 + i;
            int k = f >> 5;
            int c4 = f & 31;
            *(float4*)&Bs[k][c4 * 4] = *(const float4*)&W[(size_t)(kb + k) * 128 + c4 * 4];
        }
        __syncthreads();

#pragma unroll
        for (int k = 0; k < 16; k++) {
            float4 a0 = *(float4*)&As[k][ty * 8];
            float4 a1 = *(float4*)&As[k][ty * 8 + 4];
            float4 b0 = *(float4*)&Bs[k][tx * 8];
            float4 b1 = *(float4*)&Bs[k][tx * 8 + 4];
            float a[8] = {a0.x, a0.y, a0.z, a0.w, a1.x, a1.y, a1.z, a1.w};
            float bb[8] = {b0.x, b0.y, b0.z, b0.w, b1.x, b1.y, b1.z, b1.w};
#pragma unroll
            for (int i = 0; i < 8; i++)
#pragma unroll
                for (int j = 0; j < 8; j++) acc[i][j] = fmaf(a[i], bb[j], acc[i][j]);
        }
        __syncthreads();
    }

#pragma unroll
    for (int i = 0; i < 8; i++) {
        int r = row0 + ty * 8 + i;
        if (r >= NN) break;
        float d = g_dinv[r];
#pragma unroll
        for (int j = 0; j < 8; j += 4) {
            float4 v;
            v.x = acc[i][j + 0] * d;
            v.y = acc[i][j + 1] * d;
            v.z = acc[i][j + 2] * d;
            v.w = acc[i][j + 3] * d;
            *(float4*)&g_hs[(size_t)r * 128 + tx * 8 + j] = v;
        }
    }
}

// ---------------- SGEMM 128x64 tile (40 valid cols): layer 3 ---------------------
__global__ void __launch_bounds__(256) k_gemm40(const float* __restrict__ W, int scOff) {
    const float* __restrict__ A = g_agg;
    __shared__ float As[16][128];
    __shared__ float Bs[16][64];
    __shared__ float sc_s[128], sh_s[128];

    const int tid = threadIdx.x;
    if (tid < 128) {
        sc_s[tid] = g_sc[scOff + tid];
        sh_s[tid] = g_sc[scOff + 128 + tid];
    }
    __syncthreads();

    const int row0 = blockIdx.x * 128;
    const int tx = tid & 15;      // 16 x 4 cols = 64
    const int ty = tid >> 4;      // 16 x 8 rows = 128

    float acc[8][4];
#pragma unroll
    for (int i = 0; i < 8; i++)
#pragma unroll
        for (int j = 0; j < 4; j++) acc[i][j] = 0.f;

    for (int kb = 0; kb < 128; kb += 16) {
#pragma unroll
        for (int i = 0; i < 2; i++) {
            int f = tid * 2 + i;
            int m = f >> 2;
            int k4 = f & 3;
            int r = row0 + m;
            float4 v = make_float4(0.f, 0.f, 0.f, 0.f);
            if (r < NN) v = *(const float4*)&A[(size_t)r * 128 + kb + k4 * 4];
            int c = kb + k4 * 4;
            v.x = fmaxf(fmaf(v.x, sc_s[c + 0], sh_s[c + 0]), 0.f);
            v.y = fmaxf(fmaf(v.y, sc_s[c + 1], sh_s[c + 1]), 0.f);
            v.z = fmaxf(fmaf(v.z, sc_s[c + 2], sh_s[c + 2]), 0.f);
            v.w = fmaxf(fmaf(v.w, sc_s[c + 3], sh_s[c + 3]), 0.f);
            As[k4 * 4 + 0][m] = v.x;
            As[k4 * 4 + 1][m] = v.y;
            As[k4 * 4 + 2][m] = v.z;
            As[k4 * 4 + 3][m] = v.w;
        }
        {
            int k = tid >> 4;        // 16
            int c4 = tid & 15;       // 16 float4 = 64 cols
            float4 v = make_float4(0.f, 0.f, 0.f, 0.f);
            if (c4 * 4 < 40) v = *(const float4*)&W[(size_t)(kb + k) * 40 + c4 * 4];
            *(float4*)&Bs[k][c4 * 4] = v;
        }
        __syncthreads();

#pragma unroll
        for (int k = 0; k < 16; k++) {
            float4 a0 = *(float4*)&As[k][ty * 8];
            float4 a1 = *(float4*)&As[k][ty * 8 + 4];
            float4 bv = *(float4*)&Bs[k][tx * 4];
            float a[8] = {a0.x, a0.y, a0.z, a0.w, a1.x, a1.y, a1.z, a1.w};
#pragma unroll
            for (int i = 0; i < 8; i++) {
                acc[i][0] = fmaf(a[i], bv.x, acc[i][0]);
                acc[i][1] = fmaf(a[i], bv.y, acc[i][1]);
                acc[i][2] = fmaf(a[i], bv.z, acc[i][2]);
                acc[i][3] = fmaf(a[i], bv.w, acc[i][3]);
            }
        }
        __syncthreads();
    }

    if (tx < 10) {
#pragma unroll
        for (int i = 0; i < 8; i++) {
            int r = row0 + ty * 8 + i;
            if (r >= NN) break;
            float d = g_dinv[r];
            float4 v;
            v.x = acc[i][0] * d;
            v.y = acc[i][1] * d;
            v.z = acc[i][2] * d;
            v.w = acc[i][3] * d;
            *(float4*)&g_hs[(size_t)r * 40 + tx * 4] = v;
        }
    }
}

// ---------------- CSR aggregate (C=128): warp per node + fused bias + BN stats ----
__global__ void __launch_bounds__(256) k_agg128(const float* __restrict__ bias, int statsOff) {
    __shared__ float sstat[256];
    int tid = threadIdx.x;
    sstat[tid] = 0.f;
    __syncthreads();

    int lane = tid & 31;
    int gw = (blockIdx.x * blockDim.x + tid) >> 5;
    int nw = (gridDim.x * blockDim.x) >> 5;
    float4 b = *(const float4*)&bias[lane * 4];
    float4 s1 = make_float4(0.f, 0.f, 0.f, 0.f);
    float4 s2 = make_float4(0.f, 0.f, 0.f, 0.f);

    for (int n = gw; n < NN; n += nw) {
        float4 acc = *(const float4*)&g_hs[(size_t)n * 128 + lane * 4];  // self loop
        int beg = g_off[n], end = g_off[n + 1];
        for (int i = beg; i < end; i++) {
            int s = g_esrc[i];
            float4 v = *(const float4*)&g_hs[(size_t)s * 128 + lane * 4];
            acc.x += v.x; acc.y += v.y; acc.z += v.z; acc.w += v.w;
        }
        float d = g_dinv[n];
        float4 val;
        val.x = fmaf(acc.x, d, b.x);
        val.y = fmaf(acc.y, d, b.y);
        val.z = fmaf(acc.z, d, b.z);
        val.w = fmaf(acc.w, d, b.w);
        *(float4*)&g_agg[(size_t)n * 128 + lane * 4] = val;
        s1.x += val.x; s1.y += val.y; s1.z += val.z; s1.w += val.w;
        s2.x += val.x * val.x; s2.y += val.y * val.y;
        s2.z += val.z * val.z; s2.w += val.w * val.w;
    }

    atomicAdd(&sstat[lane * 4 + 0], s1.x);
    atomicAdd(&sstat[lane * 4 + 1], s1.y);
    atomicAdd(&sstat[lane * 4 + 2], s1.z);
    atomicAdd(&sstat[lane * 4 + 3], s1.w);
    atomicAdd(&sstat[128 + lane * 4 + 0], s2.x);
    atomicAdd(&sstat[128 + lane * 4 + 1], s2.y);
    atomicAdd(&sstat[128 + lane * 4 + 2], s2.z);
    atomicAdd(&sstat[128 + lane * 4 + 3], s2.w);
    __syncthreads();
    atomicAdd(&g_stats[statsOff + tid], sstat[tid]);
}

// ---------------- CSR aggregate (C=40): direct output write ----------------------
__global__ void __launch_bounds__(256) k_agg40(const float* __restrict__ b3,
                                               float* __restrict__ out) {
    int tid = threadIdx.x;
    int lane = tid & 31;
    int gw = (blockIdx.x * blockDim.x + tid) >> 5;
    int nw = (gridDim.x * blockDim.x) >> 5;
    bool act = lane < 10;
    float4 b = make_float4(0.f, 0.f, 0.f, 0.f);
    if (act) b = *(const float4*)&b3[lane * 4];

    for (int n = gw; n < NN; n += nw) {
        int beg = g_off[n], end = g_off[n + 1];
        float4 acc = make_float4(0.f, 0.f, 0.f, 0.f);
        if (act) acc = *(const float4*)&g_hs[(size_t)n * 40 + lane * 4];
        for (int i = beg; i < end; i++) {
            int s = g_esrc[i];
            if (act) {
                float4 v = *(const float4*)&g_hs[(size_t)s * 40 + lane * 4];
                acc.x += v.x; acc.y += v.y; acc.z += v.z; acc.w += v.w;
            }
        }
        if (act) {
            float d = g_dinv[n];
            float4 o;
            o.x = fmaf(acc.x, d, b.x);
            o.y = fmaf(acc.y, d, b.y);
            o.z = fmaf(acc.z, d, b.z);
            o.w = fmaf(acc.w, d, b.w);
            *(float4*)&out[(size_t)n * 40 + lane * 4] = o;
        }
    }
}

// ---------------- finalize BN: scale/shift per channel -----------------------------
__global__ void k_finalize(const float* __restrict__ gamma, const float* __restrict__ beta,
                           int statsOff, int scOff) {
    int c = threadIdx.x;            // 128 threads, 1 block
    float inv_n = 1.f / (float)NN;
    float mean = g_stats[statsOff + c] * inv_n;
    float var  = g_stats[statsOff + 128 + c] * inv_n - mean * mean;
    float inv  = rsqrtf(var + BN_EPS);
    float sc   = gamma[c] * inv;
    g_sc[scOff + c]       = sc;
    g_sc[scOff + 128 + c] = beta[c] - mean * sc;
}

// ---------------- launch ----------------
extern "C" void kernel_launch(void* const* d_in, const int* in_sizes, int n_in,
                              void* d_out, int out_size) {
    const float* x    = (const float*)d_in[0];
    const int*   ei32 = (const int*)d_in[1];
    const float* W1 = (const float*)d_in[2];
    const float* b1 = (const float*)d_in[3];
    const float* g1 = (const float*)d_in[4];
    const float* t1 = (const float*)d_in[5];
    const float* W2 = (const float*)d_in[6];
    const float* b2 = (const float*)d_in[7];
    const float* g2 = (const float*)d_in[8];
    const float* t2 = (const float*)d_in[9];
    const float* W3 = (const float*)d_in[10];
    const float* b3 = (const float*)d_in[11];
    float* out = (float*)d_out;

    const int gemmBlocks = (NN + 127) / 128;     // 782
    const int aggBlocks  = 1184;                 // 8 blocks/SM
    const int edgeBlocks = (NE + 255) / 256;     // 6250

    k_init<<<(NN + 255) / 256, 256>>>();
    k_detect<<<1, 1>>>(ei32);
    k_convert<<<edgeBlocks, 256>>>(ei32);
    k_dinv<<<(NN + 255) / 256, 256>>>();
    k_bsum<<<NSB, 256>>>();
    k_scanb<<<1, 1>>>();
    k_off<<<NSB, 256>>>();
    k_place<<<edgeBlocks, 256>>>();

    // layer 1
    k_gemm128<false><<<gemmBlocks, 256>>>(x, W1, 0);
    k_agg128<<<aggBlocks, 256>>>(b1, 0);
    k_finalize<<<1, 128>>>(g1, t1, 0, 0);

    // layer 2 (norm+relu fused into A-load)
    k_gemm128<true><<<gemmBlocks, 256>>>(nullptr, W2, 0);
    k_agg128<<<aggBlocks, 256>>>(b2, 256);
    k_finalize<<<1, 128>>>(g2, t2, 256, 256);

    // layer 3 (output, 40 cols)
    k_gemm40<<<gemmBlocks, 256>>>(W3, 256);
    k_agg40<<<aggBlocks, 256>>>(b3, out);
}